// round 2
// baseline (speedup 1.0000x reference)
#include <cuda_runtime.h>
#include <math.h>

// Problem constants (fixed by the reference: N=16384, S=6, C=101)
#define NCELLS (16384 * 6 * 6)   // 589824 cells
#define CHANS  106               // 5 + C
#define NPAIRS 53                // CHANS/2 (float2 pairs per cell)
#define BATCH  16384.0

// Global scratch for the 5 partial sums (xy, wh, conf_obj, conf_noobj, class).
// Device-global array (no allocation allowed in kernel_launch).
__device__ double g_acc[5];

__global__ void yolo_init_kernel() {
    if (threadIdx.x < 5) g_acc[threadIdx.x] = 0.0;
}

__global__ void __launch_bounds__(256) yolo_reduce_kernel(
    const float* __restrict__ pred,
    const float* __restrict__ targ)
{
    __shared__ float s[5];
    if (threadIdx.x < 5) s[threadIdx.x] = 0.0f;
    __syncthreads();

    const int lane  = threadIdx.x & 31;
    const int gwarp = (blockIdx.x * blockDim.x + threadIdx.x) >> 5;
    const int nwarp = (gridDim.x * blockDim.x) >> 5;

    float sxy = 0.f, swh = 0.f, sco = 0.f, scn = 0.f, scl = 0.f;

    for (int cell = gwarp; cell < NCELLS; cell += nwarp) {
        const size_t base = (size_t)cell * CHANS;
        const float2* __restrict__ p2 = (const float2*)(pred + base);
        const float2* __restrict__ t2 = (const float2*)(targ + base);

        // object mask: broadcast load of target conf channel (same addr across warp)
        const float t4  = __ldg(targ + base + 4);
        const float obj = (t4 != 0.f) ? 1.f : 0.f;

        #pragma unroll
        for (int it = 0; it < 2; it++) {
            const int p = lane + it * 32;
            if (p < NPAIRS) {
                const float2 tv = t2[p];
                const float2 pv = p2[p];
                const float dx = tv.x - pv.x;
                const float dy = tv.y - pv.y;
                if (p >= 3) {
                    // channels 6..105: class loss
                    scl += obj * (dx * dx + dy * dy);
                } else if (p == 0) {
                    // channels 0,1: xy coord loss
                    sxy += obj * (dx * dx + dy * dy);
                } else if (p == 1) {
                    // channels 2,3: wh (sqrt) loss; pred clamped >= 0
                    const float a = sqrtf(tv.x) - sqrtf(fmaxf(pv.x, 0.f));
                    const float b = sqrtf(tv.y) - sqrtf(fmaxf(pv.y, 0.f));
                    swh += obj * (a * a + b * b);
                } else {
                    // p == 2: channel 4 = confidence, channel 5 = first class
                    const float ce = dx * dx;
                    sco += obj * ce;
                    scn += (1.f - obj) * ce;
                    scl += obj * (dy * dy);
                }
            }
        }
    }

    // warp reduction of the 5 accumulators
    #pragma unroll
    for (int o = 16; o > 0; o >>= 1) {
        sxy += __shfl_xor_sync(0xFFFFFFFFu, sxy, o);
        swh += __shfl_xor_sync(0xFFFFFFFFu, swh, o);
        sco += __shfl_xor_sync(0xFFFFFFFFu, sco, o);
        scn += __shfl_xor_sync(0xFFFFFFFFu, scn, o);
        scl += __shfl_xor_sync(0xFFFFFFFFu, scl, o);
    }
    if (lane == 0) {
        atomicAdd(&s[0], sxy);
        atomicAdd(&s[1], swh);
        atomicAdd(&s[2], sco);
        atomicAdd(&s[3], scn);
        atomicAdd(&s[4], scl);
    }
    __syncthreads();
    if (threadIdx.x < 5)
        atomicAdd(&g_acc[threadIdx.x], (double)s[threadIdx.x]);
}

__global__ void yolo_final_kernel(float* __restrict__ out) {
    const double inv = 1.0 / BATCH;
    const double lxy = g_acc[0] * inv;
    const double lwh = g_acc[1] * inv;
    const double lco = g_acc[2] * inv;
    const double lcn = g_acc[3] * inv;
    const double lcl = g_acc[4] * inv;
    const double loss = (5.0 * lxy + 5.0 * lwh + lco + 0.5 * lcn + lcl) * inv;
    out[0] = (float)lxy;
    out[1] = (float)lwh;
    out[2] = (float)lco;
    out[3] = (float)lcn;
    out[4] = (float)lcl;
    out[5] = (float)loss;
}

extern "C" void kernel_launch(void* const* d_in, const int* in_sizes, int n_in,
                              void* d_out, int out_size) {
    const float* pred = (const float*)d_in[0];
    const float* targ = (const float*)d_in[1];
    float* out = (float*)d_out;

    yolo_init_kernel<<<1, 32>>>();

    // 148-SM class chip; 8 blocks/SM x 256 threads gives ample MLP for the
    // streaming reduction while keeping per-lane accumulation chains short.
    const int blocks = 148 * 8;
    yolo_reduce_kernel<<<blocks, 256>>>(pred, targ);

    yolo_final_kernel<<<1, 1>>>(out);
}